// round 4
// baseline (speedup 1.0000x reference)
#include <cuda_runtime.h>
#include <cstdint>
#include <cstddef>

// ---------------------------------------------------------------------------
// HyperConv: y[b,o,t] = bias[chunk,o] + sum_{tap,cin} x[b,cin,t-tap] * W[chunk, (tap*128+cin)*128+o]
// chunk = b*400 + (t/120); W = w2 @ relu(w1 @ z + b1) + b2 (per chunk)
// ---------------------------------------------------------------------------

#define NB   4
#define ZD   64
#define NK   400
#define TT   48000
#define CI   128
#define CO   128
#define KSZ  3
#define HH   32
#define TKC  120                    // samples per chunk
#define NCH  (NB*NK)                // 1600 chunks
#define RD   (CI*KSZ*CO)            // 49152 rows of w2

// scratch: per-chunk generated weights, chunk-major [chunk][cidx*128+o]
__device__ float g_W[(size_t)NCH * RD];      // 314.6 MB
__device__ float g_hv[NCH * HH];
__device__ float g_bias[NCH * CO];

// ---------------------------------------------------------------------------
// Kernel 1: per-chunk MLP hiddens + bias vector
// ---------------------------------------------------------------------------
__global__ __launch_bounds__(128) void prep_kernel(
    const float* __restrict__ z,
    const float* __restrict__ w1, const float* __restrict__ b1,
    const float* __restrict__ bw1, const float* __restrict__ bb1,
    const float* __restrict__ bw2, const float* __restrict__ bb2)
{
    int chunk = blockIdx.x;
    int b = chunk / NK, kk = chunk % NK;
    __shared__ float zv[ZD];
    __shared__ float hb[HH];
    int tid = threadIdx.x;
    if (tid < ZD) zv[tid] = z[((size_t)b * ZD + tid) * NK + kk];
    __syncthreads();
    if (tid < HH) {
        float s = b1[tid];
        #pragma unroll 8
        for (int j = 0; j < ZD; j++) s += w1[tid * ZD + j] * zv[j];
        g_hv[chunk * HH + tid] = fmaxf(s, 0.f);
    } else if (tid < 2 * HH) {
        int o = tid - HH;
        float s = bb1[o];
        #pragma unroll 8
        for (int j = 0; j < ZD; j++) s += bw1[o * ZD + j] * zv[j];
        hb[o] = fmaxf(s, 0.f);
    }
    __syncthreads();
    {
        float s = bb2[tid];
        #pragma unroll
        for (int h = 0; h < HH; h++) s += bw2[tid * HH + h] * hb[h];
        g_bias[chunk * CO + tid] = s;
    }
}

// ---------------------------------------------------------------------------
// Kernel 2: weight generation GEMM  g_W[c][r] = sum_h w2[r][h]*hv[c][h] + b2[r]
// M=49152 (r), N=1600 (chunk), K=32.  Block tile 128r x 128c, thread 16r x 4c.
// ---------------------------------------------------------------------------
__global__ __launch_bounds__(256) void wgen_kernel(
    const float* __restrict__ w2, const float* __restrict__ b2)
{
    __shared__ __align__(16) float as[HH * 132];   // [k][r], padded
    __shared__ __align__(16) float bs[HH * 132];   // [k][c], padded
    int tid = threadIdx.x;
    int r0 = blockIdx.x * 128;
    int c0 = blockIdx.y * 128;

    // load w2 tile (transposed into k-major)
    for (int i4 = tid; i4 < 1024; i4 += 256) {
        int r = i4 >> 3, h4 = i4 & 7;
        float4 v = *(const float4*)(w2 + (size_t)(r0 + r) * HH + h4 * 4);
        as[(h4 * 4 + 0) * 132 + r] = v.x;
        as[(h4 * 4 + 1) * 132 + r] = v.y;
        as[(h4 * 4 + 2) * 132 + r] = v.z;
        as[(h4 * 4 + 3) * 132 + r] = v.w;
    }
    // load hv tile (transposed into k-major), clamp OOB chunks
    for (int i4 = tid; i4 < 1024; i4 += 256) {
        int c = i4 >> 3, h4 = i4 & 7;
        int cc = c0 + c; if (cc >= NCH) cc = NCH - 1;
        float4 v = *(const float4*)(g_hv + (size_t)cc * HH + h4 * 4);
        bs[(h4 * 4 + 0) * 132 + c] = v.x;
        bs[(h4 * 4 + 1) * 132 + c] = v.y;
        bs[(h4 * 4 + 2) * 132 + c] = v.z;
        bs[(h4 * 4 + 3) * 132 + c] = v.w;
    }
    __syncthreads();

    int tx = tid & 31;          // chunk sub-tile: c = c0 + tx*4 + j
    int ty = tid >> 5;          // row sub-tile (== warp id): r = r0 + ty*16 + i
    float acc[4][16];
    #pragma unroll
    for (int j = 0; j < 4; j++)
        #pragma unroll
        for (int i = 0; i < 16; i++) acc[j][i] = 0.f;

    #pragma unroll 8
    for (int k = 0; k < HH; k++) {
        const float* ar = as + k * 132 + ty * 16;   // warp-uniform (broadcast)
        float av[16];
        #pragma unroll
        for (int u = 0; u < 4; u++) {
            float4 v = *(const float4*)(ar + u * 4);
            av[u * 4 + 0] = v.x; av[u * 4 + 1] = v.y;
            av[u * 4 + 2] = v.z; av[u * 4 + 3] = v.w;
        }
        float4 bq = *(const float4*)(bs + k * 132 + tx * 4);
        float bv[4] = {bq.x, bq.y, bq.z, bq.w};
        #pragma unroll
        for (int j = 0; j < 4; j++)
            #pragma unroll
            for (int i = 0; i < 16; i++)
                acc[j][i] += bv[j] * av[i];
    }

    float bias[16];
    #pragma unroll
    for (int u = 0; u < 4; u++) {
        float4 v = *(const float4*)(b2 + r0 + ty * 16 + u * 4);
        bias[u * 4 + 0] = v.x; bias[u * 4 + 1] = v.y;
        bias[u * 4 + 2] = v.z; bias[u * 4 + 3] = v.w;
    }
    #pragma unroll
    for (int j = 0; j < 4; j++) {
        int c = c0 + tx * 4 + j;
        if (c < NCH) {
            float* dst = g_W + (size_t)c * RD + r0 + ty * 16;
            #pragma unroll
            for (int u = 0; u < 4; u++) {
                float4 o;
                o.x = acc[j][u * 4 + 0] + bias[u * 4 + 0];
                o.y = acc[j][u * 4 + 1] + bias[u * 4 + 1];
                o.z = acc[j][u * 4 + 2] + bias[u * 4 + 2];
                o.w = acc[j][u * 4 + 3] + bias[u * 4 + 3];
                *(float4*)(dst + u * 4) = o;
            }
        }
    }
}

// ---------------------------------------------------------------------------
// Kernel 3: per-chunk conv GEMM [120 x 384] @ [384 x 128]
// One block per chunk, 256 threads. x tile in smem, W staged by cp.async
// (double-buffered, 32 cin x 3 taps per stage). Thread: 15 contiguous t x 4 o.
// 3 taps share x values (17 loads feed 180 FFMA per cin).
// ---------------------------------------------------------------------------
#define XS_STRIDE 124
#define XS_FLOATS (CI * XS_STRIDE)            // 15872
#define WB_FLOATS (KSZ * 32 * CO)             // 12288 per buffer
#define CONV_SMEM_BYTES ((XS_FLOATS + 2 * WB_FLOATS) * 4)   // 161792 B

__device__ __forceinline__ void cp_async16(float* dst, const float* src) {
    unsigned s = (unsigned)__cvta_generic_to_shared(dst);
    asm volatile("cp.async.cg.shared.global [%0], [%1], 16;" :: "r"(s), "l"(src));
}
__device__ __forceinline__ void cp_commit() {
    asm volatile("cp.async.commit_group;");
}

__global__ __launch_bounds__(256, 1) void conv_kernel(
    const float* __restrict__ x, float* __restrict__ out)
{
    extern __shared__ __align__(16) float sm[];
    float* xs = sm;                      // [CI][XS_STRIDE], j = t - t0 + 2
    float* wb = sm + XS_FLOATS;          // [2][3][32][128]

    int chunk = blockIdx.x;
    int b = chunk / NK, kk = chunk % NK;
    int t0 = kk * TKC;
    int tid = threadIdx.x, lane = tid & 31, warp = tid >> 5;

    const float* Wc = g_W + (size_t)chunk * RD;

    // stage cb=0 weights
    #pragma unroll
    for (int i = 0; i < 12; i++) {
        int i4 = tid + i * 256;              // 0..3071 float4s
        int tap = i4 >> 10, rem = i4 & 1023;
        cp_async16(wb + tap * 4096 + rem * 4,
                   Wc + ((size_t)(tap * CI + 0 * 32) * CO) + rem * 4);
    }
    cp_commit();

    // load x tile: j in [0,122), t = t0 - 2 + j  (zero-pad t<0)
    const float* xb = x + (size_t)b * CI * TT;
    for (int idx = tid; idx < CI * 122; idx += 256) {
        int cin = idx / 122, j = idx - cin * 122;
        int t = t0 - 2 + j;
        xs[cin * XS_STRIDE + j] = (t >= 0) ? xb[(size_t)cin * TT + t] : 0.f;
    }

    // accumulators init with bias (broadcast over t)
    float acc[15][4];
    float4 bv = *(const float4*)(g_bias + (size_t)chunk * CO + lane * 4);
    #pragma unroll
    for (int r = 0; r < 15; r++) {
        acc[r][0] = bv.x; acc[r][1] = bv.y; acc[r][2] = bv.z; acc[r][3] = bv.w;
    }

    int tb = warp * 15;   // this warp's first t (contiguous 15 samples)

    for (int cb = 0; cb < 4; cb++) {
        if (cb < 3) {
            float* nbuf = wb + ((cb + 1) & 1) * WB_FLOATS;
            #pragma unroll
            for (int i = 0; i < 12; i++) {
                int i4 = tid + i * 256;
                int tap = i4 >> 10, rem = i4 & 1023;
                cp_async16(nbuf + tap * 4096 + rem * 4,
                           Wc + ((size_t)(tap * CI + (cb + 1) * 32) * CO) + rem * 4);
            }
            cp_commit();
            asm volatile("cp.async.wait_group 1;");
        } else {
            asm volatile("cp.async.wait_group 0;");
        }
        __syncthreads();   // current buffer (and xs on cb==0) ready

        const float* wbp = wb + (cb & 1) * WB_FLOATS;
        #pragma unroll 2
        for (int cl = 0; cl < 32; cl++) {
            int cin = cb * 32 + cl;
            const float* xp = xs + cin * XS_STRIDE + tb;
            float xv[17];
            #pragma unroll
            for (int m = 0; m < 17; m++) xv[m] = xp[m];   // broadcast LDS

            float4 w0 = *(const float4*)(wbp + (0 * 32 + cl) * CO + lane * 4);
            float4 w1 = *(const float4*)(wbp + (1 * 32 + cl) * CO + lane * 4);
            float4 w2v = *(const float4*)(wbp + (2 * 32 + cl) * CO + lane * 4);

            #pragma unroll
            for (int r = 0; r < 15; r++) {
                // tap 0 uses x[t], tap 1 x[t-1], tap 2 x[t-2]; j = t - t0 + 2
                float x2 = xv[r + 2], x1 = xv[r + 1], x0 = xv[r];
                acc[r][0] += x2 * w0.x; acc[r][0] += x1 * w1.x; acc[r][0] += x0 * w2v.x;
                acc[r][1] += x2 * w0.y; acc[r][1] += x1 * w1.y; acc[r][1] += x0 * w2v.y;
                acc[r][2] += x2 * w0.z; acc[r][2] += x1 * w1.z; acc[r][2] += x0 * w2v.z;
                acc[r][3] += x2 * w0.w; acc[r][3] += x1 * w1.w; acc[r][3] += x0 * w2v.w;
            }
        }
        __syncthreads();   // done reading this buffer before it is overwritten
    }

    // epilogue: out[b, o, t0+tb+r], o = lane*4+q — 15 contiguous floats per (o)
    float* ob = out + (size_t)b * CO * TT + t0 + tb;
    #pragma unroll
    for (int q = 0; q < 4; q++) {
        float* op = ob + (size_t)(lane * 4 + q) * TT;
        #pragma unroll
        for (int r = 0; r < 15; r++) op[r] = acc[r][q];
    }
}

// ---------------------------------------------------------------------------
extern "C" void kernel_launch(void* const* d_in, const int* in_sizes, int n_in,
                              void* d_out, int out_size)
{
    const float* x   = (const float*)d_in[0];
    const float* z   = (const float*)d_in[1];
    const float* w1  = (const float*)d_in[2];
    const float* b1  = (const float*)d_in[3];
    const float* w2  = (const float*)d_in[4];
    const float* b2  = (const float*)d_in[5];
    const float* bw1 = (const float*)d_in[6];
    const float* bb1 = (const float*)d_in[7];
    const float* bw2 = (const float*)d_in[8];
    const float* bb2 = (const float*)d_in[9];
    float* out = (float*)d_out;

    cudaFuncSetAttribute(conv_kernel,
                         cudaFuncAttributeMaxDynamicSharedMemorySize,
                         CONV_SMEM_BYTES);

    prep_kernel<<<NCH, 128>>>(z, w1, b1, bw1, bb1, bw2, bb2);
    wgen_kernel<<<dim3(RD / 128, (NCH + 127) / 128), 256>>>(w2, b2);
    conv_kernel<<<NCH, 256, CONV_SMEM_BYTES>>>(x, out);
}

// round 5
// speedup vs baseline: 1.0046x; 1.0046x over previous
#include <cuda_runtime.h>
#include <cstdint>
#include <cstddef>

// ---------------------------------------------------------------------------
// HyperConv: y[b,o,t] = bias[chunk,o] + sum_{tap,cin} x[b,cin,t-tap] * W[chunk, (tap*128+cin)*128+o]
// chunk = b*400 + (t/120); W = w2 @ relu(w1 @ z + b1) + b2 (per chunk)
// ---------------------------------------------------------------------------

#define NB   4
#define ZD   64
#define NK   400
#define TT   48000
#define CI   128
#define CO   128
#define KSZ  3
#define HH   32
#define TKC  120                    // samples per chunk
#define NCH  (NB*NK)                // 1600 chunks
#define RD   (CI*KSZ*CO)            // 49152 rows of w2

// scratch: per-chunk generated weights, chunk-major [chunk][cidx*128+o]
__device__ float g_W[(size_t)NCH * RD];      // 314.6 MB
__device__ float g_hv[NCH * HH];
__device__ float g_bias[NCH * CO];

// ---------------------------------------------------------------------------
// Kernel 1: per-chunk MLP hiddens + bias vector
// ---------------------------------------------------------------------------
__global__ __launch_bounds__(128) void prep_kernel(
    const float* __restrict__ z,
    const float* __restrict__ w1, const float* __restrict__ b1,
    const float* __restrict__ bw1, const float* __restrict__ bb1,
    const float* __restrict__ bw2, const float* __restrict__ bb2)
{
    int chunk = blockIdx.x;
    int b = chunk / NK, kk = chunk % NK;
    __shared__ float zv[ZD];
    __shared__ float hb[HH];
    int tid = threadIdx.x;
    if (tid < ZD) zv[tid] = z[((size_t)b * ZD + tid) * NK + kk];
    __syncthreads();
    if (tid < HH) {
        float s = b1[tid];
        #pragma unroll 8
        for (int j = 0; j < ZD; j++) s += w1[tid * ZD + j] * zv[j];
        g_hv[chunk * HH + tid] = fmaxf(s, 0.f);
    } else if (tid < 2 * HH) {
        int o = tid - HH;
        float s = bb1[o];
        #pragma unroll 8
        for (int j = 0; j < ZD; j++) s += bw1[o * ZD + j] * zv[j];
        hb[o] = fmaxf(s, 0.f);
    }
    __syncthreads();
    {
        float s = bb2[tid];
        #pragma unroll
        for (int h = 0; h < HH; h++) s += bw2[tid * HH + h] * hb[h];
        g_bias[chunk * CO + tid] = s;
    }
}

// ---------------------------------------------------------------------------
// Kernel 2: weight generation GEMM  g_W[c][r] = sum_h w2[r][h]*hv[c][h] + b2[r]
// M=49152 (r), N=1600 (chunk), K=32.  Block tile 128r x 128c, thread 16r x 4c.
// ---------------------------------------------------------------------------
__global__ __launch_bounds__(256) void wgen_kernel(
    const float* __restrict__ w2, const float* __restrict__ b2)
{
    __shared__ __align__(16) float as[HH * 132];   // [k][r], padded
    __shared__ __align__(16) float bs[HH * 132];   // [k][c], padded
    int tid = threadIdx.x;
    int r0 = blockIdx.x * 128;
    int c0 = blockIdx.y * 128;

    // load w2 tile (transposed into k-major)
    for (int i4 = tid; i4 < 1024; i4 += 256) {
        int r = i4 >> 3, h4 = i4 & 7;
        float4 v = *(const float4*)(w2 + (size_t)(r0 + r) * HH + h4 * 4);
        as[(h4 * 4 + 0) * 132 + r] = v.x;
        as[(h4 * 4 + 1) * 132 + r] = v.y;
        as[(h4 * 4 + 2) * 132 + r] = v.z;
        as[(h4 * 4 + 3) * 132 + r] = v.w;
    }
    // load hv tile (transposed into k-major), clamp OOB chunks
    for (int i4 = tid; i4 < 1024; i4 += 256) {
        int c = i4 >> 3, h4 = i4 & 7;
        int cc = c0 + c; if (cc >= NCH) cc = NCH - 1;
        float4 v = *(const float4*)(g_hv + (size_t)cc * HH + h4 * 4);
        bs[(h4 * 4 + 0) * 132 + c] = v.x;
        bs[(h4 * 4 + 1) * 132 + c] = v.y;
        bs[(h4 * 4 + 2) * 132 + c] = v.z;
        bs[(h4 * 4 + 3) * 132 + c] = v.w;
    }
    __syncthreads();

    int tx = tid & 31;          // chunk sub-tile: c = c0 + tx*4 + j
    int ty = tid >> 5;          // row sub-tile (== warp id): r = r0 + ty*16 + i
    float acc[4][16];
    #pragma unroll
    for (int j = 0; j < 4; j++)
        #pragma unroll
        for (int i = 0; i < 16; i++) acc[j][i] = 0.f;

    #pragma unroll 8
    for (int k = 0; k < HH; k++) {
        const float* ar = as + k * 132 + ty * 16;   // warp-uniform (broadcast)
        float av[16];
        #pragma unroll
        for (int u = 0; u < 4; u++) {
            float4 v = *(const float4*)(ar + u * 4);
            av[u * 4 + 0] = v.x; av[u * 4 + 1] = v.y;
            av[u * 4 + 2] = v.z; av[u * 4 + 3] = v.w;
        }
        float4 bq = *(const float4*)(bs + k * 132 + tx * 4);
        float bv[4] = {bq.x, bq.y, bq.z, bq.w};
        #pragma unroll
        for (int j = 0; j < 4; j++)
            #pragma unroll
            for (int i = 0; i < 16; i++)
                acc[j][i] += bv[j] * av[i];
    }

    float bias[16];
    #pragma unroll
    for (int u = 0; u < 4; u++) {
        float4 v = *(const float4*)(b2 + r0 + ty * 16 + u * 4);
        bias[u * 4 + 0] = v.x; bias[u * 4 + 1] = v.y;
        bias[u * 4 + 2] = v.z; bias[u * 4 + 3] = v.w;
    }
    #pragma unroll
    for (int j = 0; j < 4; j++) {
        int c = c0 + tx * 4 + j;
        if (c < NCH) {
            float* dst = g_W + (size_t)c * RD + r0 + ty * 16;
            #pragma unroll
            for (int u = 0; u < 4; u++) {
                float4 o;
                o.x = acc[j][u * 4 + 0] + bias[u * 4 + 0];
                o.y = acc[j][u * 4 + 1] + bias[u * 4 + 1];
                o.z = acc[j][u * 4 + 2] + bias[u * 4 + 2];
                o.w = acc[j][u * 4 + 3] + bias[u * 4 + 3];
                *(float4*)(dst + u * 4) = o;
            }
        }
    }
}

// ---------------------------------------------------------------------------
// Kernel 3: per-chunk conv GEMM [120 x 384] @ [384 x 128]
// One block per chunk, 256 threads. x tile in smem, W staged by cp.async
// (double-buffered, 32 cin x 3 taps per stage). Thread: 15 contiguous t x 4 o.
// 3 taps share x values (17 loads feed 180 FFMA per cin).
// ---------------------------------------------------------------------------
#define XS_STRIDE 124
#define XS_FLOATS (CI * XS_STRIDE)            // 15872
#define WB_FLOATS (KSZ * 32 * CO)             // 12288 per buffer
#define CONV_SMEM_BYTES ((XS_FLOATS + 2 * WB_FLOATS) * 4)   // 161792 B

__device__ __forceinline__ void cp_async16(float* dst, const float* src) {
    unsigned s = (unsigned)__cvta_generic_to_shared(dst);
    asm volatile("cp.async.cg.shared.global [%0], [%1], 16;" :: "r"(s), "l"(src));
}
__device__ __forceinline__ void cp_commit() {
    asm volatile("cp.async.commit_group;");
}

__global__ __launch_bounds__(256, 1) void conv_kernel(
    const float* __restrict__ x, float* __restrict__ out)
{
    extern __shared__ __align__(16) float sm[];
    float* xs = sm;                      // [CI][XS_STRIDE], j = t - t0 + 2
    float* wb = sm + XS_FLOATS;          // [2][3][32][128]

    int chunk = blockIdx.x;
    int b = chunk / NK, kk = chunk % NK;
    int t0 = kk * TKC;
    int tid = threadIdx.x, lane = tid & 31, warp = tid >> 5;

    const float* Wc = g_W + (size_t)chunk * RD;

    // stage cb=0 weights
    #pragma unroll
    for (int i = 0; i < 12; i++) {
        int i4 = tid + i * 256;              // 0..3071 float4s
        int tap = i4 >> 10, rem = i4 & 1023;
        cp_async16(wb + tap * 4096 + rem * 4,
                   Wc + ((size_t)(tap * CI + 0 * 32) * CO) + rem * 4);
    }
    cp_commit();

    // load x tile: j in [0,122), t = t0 - 2 + j  (zero-pad t<0)
    const float* xb = x + (size_t)b * CI * TT;
    for (int idx = tid; idx < CI * 122; idx += 256) {
        int cin = idx / 122, j = idx - cin * 122;
        int t = t0 - 2 + j;
        xs[cin * XS_STRIDE + j] = (t >= 0) ? xb[(size_t)cin * TT + t] : 0.f;
    }

    // accumulators init with bias (broadcast over t)
    float acc[15][4];
    float4 bv = *(const float4*)(g_bias + (size_t)chunk * CO + lane * 4);
    #pragma unroll
    for (int r = 0; r < 15; r++) {
        acc[r][0] = bv.x; acc[r][1] = bv.y; acc[r][2] = bv.z; acc[r][3] = bv.w;
    }

    int tb = warp * 15;   // this warp's first t (contiguous 15 samples)

    for (int cb = 0; cb < 4; cb++) {
        if (cb < 3) {
            float* nbuf = wb + ((cb + 1) & 1) * WB_FLOATS;
            #pragma unroll
            for (int i = 0; i < 12; i++) {
                int i4 = tid + i * 256;
                int tap = i4 >> 10, rem = i4 & 1023;
                cp_async16(nbuf + tap * 4096 + rem * 4,
                           Wc + ((size_t)(tap * CI + (cb + 1) * 32) * CO) + rem * 4);
            }
            cp_commit();
            asm volatile("cp.async.wait_group 1;");
        } else {
            asm volatile("cp.async.wait_group 0;");
        }
        __syncthreads();   // current buffer (and xs on cb==0) ready

        const float* wbp = wb + (cb & 1) * WB_FLOATS;
        #pragma unroll 2
        for (int cl = 0; cl < 32; cl++) {
            int cin = cb * 32 + cl;
            const float* xp = xs + cin * XS_STRIDE + tb;
            float xv[17];
            #pragma unroll
            for (int m = 0; m < 17; m++) xv[m] = xp[m];   // broadcast LDS

            float4 w0 = *(const float4*)(wbp + (0 * 32 + cl) * CO + lane * 4);
            float4 w1 = *(const float4*)(wbp + (1 * 32 + cl) * CO + lane * 4);
            float4 w2v = *(const float4*)(wbp + (2 * 32 + cl) * CO + lane * 4);

            #pragma unroll
            for (int r = 0; r < 15; r++) {
                // tap 0 uses x[t], tap 1 x[t-1], tap 2 x[t-2]; j = t - t0 + 2
                float x2 = xv[r + 2], x1 = xv[r + 1], x0 = xv[r];
                acc[r][0] += x2 * w0.x; acc[r][0] += x1 * w1.x; acc[r][0] += x0 * w2v.x;
                acc[r][1] += x2 * w0.y; acc[r][1] += x1 * w1.y; acc[r][1] += x0 * w2v.y;
                acc[r][2] += x2 * w0.z; acc[r][2] += x1 * w1.z; acc[r][2] += x0 * w2v.z;
                acc[r][3] += x2 * w0.w; acc[r][3] += x1 * w1.w; acc[r][3] += x0 * w2v.w;
            }
        }
        __syncthreads();   // done reading this buffer before it is overwritten
    }

    // epilogue: out[b, o, t0+tb+r], o = lane*4+q — 15 contiguous floats per (o)
    float* ob = out + (size_t)b * CO * TT + t0 + tb;
    #pragma unroll
    for (int q = 0; q < 4; q++) {
        float* op = ob + (size_t)(lane * 4 + q) * TT;
        #pragma unroll
        for (int r = 0; r < 15; r++) op[r] = acc[r][q];
    }
}

// ---------------------------------------------------------------------------
extern "C" void kernel_launch(void* const* d_in, const int* in_sizes, int n_in,
                              void* d_out, int out_size)
{
    const float* x   = (const float*)d_in[0];
    const float* z   = (const float*)d_in[1];
    const float* w1  = (const float*)d_in[2];
    const float* b1  = (const float*)d_in[3];
    const float* w2  = (const float*)d_in[4];
    const float* b2  = (const float*)d_in[5];
    const float* bw1 = (const float*)d_in[6];
    const float* bb1 = (const float*)d_in[7];
    const float* bw2 = (const float*)d_in[8];
    const float* bb2 = (const float*)d_in[9];
    float* out = (float*)d_out;

    cudaFuncSetAttribute(conv_kernel,
                         cudaFuncAttributeMaxDynamicSharedMemorySize,
                         CONV_SMEM_BYTES);

    prep_kernel<<<NCH, 128>>>(z, w1, b1, bw1, bb1, bw2, bb2);
    wgen_kernel<<<dim3(RD / 128, (NCH + 127) / 128), 256>>>(w2, b2);
    conv_kernel<<<NCH, 256, CONV_SMEM_BYTES>>>(x, out);
}

// round 7
// speedup vs baseline: 2.1809x; 2.1709x over previous
#include <cuda_runtime.h>
#include <cstdint>
#include <cstddef>

#define NB   4
#define ZD   64
#define NK   400
#define TT   48000
#define CI   128
#define CO   128
#define KSZ  3
#define HH   32
#define TKC  120
#define NCH  (NB*NK)                 // 1600
#define RD   (CI*KSZ*CO)             // 49152

// ---------------- device scratch ----------------
__device__ float g_W[(size_t)NCH * RD];      // tf32-rounded weights [chunk][tap*CI+cin][co]
__device__ float g_hv[NCH * HH];
__device__ float g_bias[NCH * CO];
__device__ float g_xt[(size_t)NB * CI * TT]; // tf32-rounded x, native layout

// ---------------- helpers ----------------
__device__ __forceinline__ uint32_t s2u(const void* p) {
    uint32_t a;
    asm("{ .reg .u64 t; cvta.to.shared.u64 t, %1; cvt.u32.u64 %0, t; }" : "=r"(a) : "l"(p));
    return a;
}
__device__ __forceinline__ void cp16(void* d, const void* s) {
    asm volatile("cp.async.cg.shared.global [%0], [%1], 16;" :: "r"(s2u(d)), "l"(s));
}
__device__ __forceinline__ void cp16z(void* d, const void* s, int sz) {
    asm volatile("cp.async.cg.shared.global [%0], [%1], 16, %2;" :: "r"(s2u(d)), "l"(s), "r"(sz));
}
__device__ __forceinline__ float to_tf32(float v) {
    uint32_t r;
    asm("cvt.rna.tf32.f32 %0, %1;" : "=r"(r) : "f"(v));
    return __uint_as_float(r);
}
__device__ __forceinline__ void mma_tf32(float* d, const uint32_t* a, uint32_t b0, uint32_t b1) {
    asm volatile(
        "mma.sync.aligned.m16n8k8.row.col.f32.tf32.tf32.f32 "
        "{%0,%1,%2,%3}, {%4,%5,%6,%7}, {%8,%9}, {%0,%1,%2,%3};"
        : "+f"(d[0]), "+f"(d[1]), "+f"(d[2]), "+f"(d[3])
        : "r"(a[0]), "r"(a[1]), "r"(a[2]), "r"(a[3]), "r"(b0), "r"(b1));
}

// ---------------------------------------------------------------------------
// Kernel 1: MLP hiddens + bias. 4 chunks/block, MLP weights staged in smem.
// ---------------------------------------------------------------------------
__global__ __launch_bounds__(256) void prep_kernel(
    const float* __restrict__ z,
    const float* __restrict__ w1, const float* __restrict__ b1,
    const float* __restrict__ bw1, const float* __restrict__ bb1,
    const float* __restrict__ bw2, const float* __restrict__ bb2)
{
    __shared__ float w1s[HH * ZD], bw1s[HH * ZD], bw2s[CO * HH];
    __shared__ float zv[4][ZD], hb[4][HH];
    int tid = threadIdx.x;
    for (int i = tid; i < HH * ZD; i += 256) { w1s[i] = w1[i]; bw1s[i] = bw1[i]; }
    for (int i = tid; i < CO * HH; i += 256) bw2s[i] = bw2[i];
    int c0 = blockIdx.x * 4;
    {
        int j = tid >> 6, zi = tid & 63;
        int chunk = c0 + j, b = chunk / NK, kk = chunk % NK;
        zv[j][zi] = z[((size_t)b * ZD + zi) * NK + kk];
    }
    __syncthreads();
    if (tid < 128) {
        int j = tid >> 5, h = tid & 31;
        float s = b1[h];
        #pragma unroll 8
        for (int q = 0; q < ZD; q++) s += w1s[h * ZD + q] * zv[j][q];
        g_hv[(c0 + j) * HH + h] = fmaxf(s, 0.f);
    } else {
        int j = (tid - 128) >> 5, h = (tid - 128) & 31;
        float s = bb1[h];
        #pragma unroll 8
        for (int q = 0; q < ZD; q++) s += bw1s[h * ZD + q] * zv[j][q];
        hb[j][h] = fmaxf(s, 0.f);
    }
    __syncthreads();
    #pragma unroll
    for (int it = 0; it < 2; it++) {
        int idx = tid + it * 256;
        int j = idx >> 7, o = idx & 127;
        float s = bb2[o];
        #pragma unroll
        for (int q = 0; q < HH; q++) s += bw2s[o * HH + q] * hb[j][q];
        g_bias[(c0 + j) * CO + o] = s;
    }
}

// ---------------------------------------------------------------------------
// Kernel 2: x -> tf32-rounded copy (same layout)
// ---------------------------------------------------------------------------
__global__ __launch_bounds__(256) void xprep_kernel(const float* __restrict__ x)
{
    size_t i0 = (size_t)blockIdx.x * 256 + threadIdx.x;
    const float4* src = (const float4*)x;
    float4* dst = (float4*)g_xt;
    #pragma unroll
    for (int u = 0; u < 4; u++) {
        size_t i = i0 + (size_t)u * 1536000;    // total 6,144,000 float4s
        float4 v = src[i];
        v.x = to_tf32(v.x); v.y = to_tf32(v.y);
        v.z = to_tf32(v.z); v.w = to_tf32(v.w);
        dst[i] = v;
    }
}

// ---------------------------------------------------------------------------
// Kernel 3: weight-gen GEMM (proven R4 kernel) + tf32 rounding in epilogue
// ---------------------------------------------------------------------------
__global__ __launch_bounds__(256) void wgen_kernel(
    const float* __restrict__ w2, const float* __restrict__ b2)
{
    __shared__ __align__(16) float as[HH * 132];
    __shared__ __align__(16) float bs[HH * 132];
    int tid = threadIdx.x;
    int r0 = blockIdx.x * 128;
    int c0 = blockIdx.y * 128;

    for (int i4 = tid; i4 < 1024; i4 += 256) {
        int r = i4 >> 3, h4 = i4 & 7;
        float4 v = *(const float4*)(w2 + (size_t)(r0 + r) * HH + h4 * 4);
        as[(h4 * 4 + 0) * 132 + r] = v.x;
        as[(h4 * 4 + 1) * 132 + r] = v.y;
        as[(h4 * 4 + 2) * 132 + r] = v.z;
        as[(h4 * 4 + 3) * 132 + r] = v.w;
    }
    for (int i4 = tid; i4 < 1024; i4 += 256) {
        int c = i4 >> 3, h4 = i4 & 7;
        int cc = c0 + c; if (cc >= NCH) cc = NCH - 1;
        float4 v = *(const float4*)(g_hv + (size_t)cc * HH + h4 * 4);
        bs[(h4 * 4 + 0) * 132 + c] = v.x;
        bs[(h4 * 4 + 1) * 132 + c] = v.y;
        bs[(h4 * 4 + 2) * 132 + c] = v.z;
        bs[(h4 * 4 + 3) * 132 + c] = v.w;
    }
    __syncthreads();

    int tx = tid & 31, ty = tid >> 5;
    float acc[4][16];
    #pragma unroll
    for (int j = 0; j < 4; j++)
        #pragma unroll
        for (int i = 0; i < 16; i++) acc[j][i] = 0.f;

    #pragma unroll 8
    for (int k = 0; k < HH; k++) {
        const float* ar = as + k * 132 + ty * 16;
        float av[16];
        #pragma unroll
        for (int u = 0; u < 4; u++) {
            float4 v = *(const float4*)(ar + u * 4);
            av[u * 4 + 0] = v.x; av[u * 4 + 1] = v.y;
            av[u * 4 + 2] = v.z; av[u * 4 + 3] = v.w;
        }
        float4 bq = *(const float4*)(bs + k * 132 + tx * 4);
        float bv[4] = {bq.x, bq.y, bq.z, bq.w};
        #pragma unroll
        for (int j = 0; j < 4; j++)
            #pragma unroll
            for (int i = 0; i < 16; i++)
                acc[j][i] += bv[j] * av[i];
    }

    float bias[16];
    #pragma unroll
    for (int u = 0; u < 4; u++) {
        float4 v = *(const float4*)(b2 + r0 + ty * 16 + u * 4);
        bias[u * 4 + 0] = v.x; bias[u * 4 + 1] = v.y;
        bias[u * 4 + 2] = v.z; bias[u * 4 + 3] = v.w;
    }
    #pragma unroll
    for (int j = 0; j < 4; j++) {
        int c = c0 + tx * 4 + j;
        if (c < NCH) {
            float* dst = g_W + (size_t)c * RD + r0 + ty * 16;
            #pragma unroll
            for (int u = 0; u < 4; u++) {
                float4 o;
                o.x = to_tf32(acc[j][u * 4 + 0] + bias[u * 4 + 0]);
                o.y = to_tf32(acc[j][u * 4 + 1] + bias[u * 4 + 1]);
                o.z = to_tf32(acc[j][u * 4 + 2] + bias[u * 4 + 2]);
                o.w = to_tf32(acc[j][u * 4 + 3] + bias[u * 4 + 3]);
                *(float4*)(dst + u * 4) = o;
            }
        }
    }
}

// ---------------------------------------------------------------------------
// Kernel 4: conv via mma.sync tf32. 1 CTA/chunk, 256 thr (8 warps, 4co x 2t).
// x tile [128 cin][128 t] resident (halo 8, stride 136 = conflict-free frags);
// W streamed in 6 stages of [64 cin][128 co], double-buffered cp.async.
// ---------------------------------------------------------------------------
#define PD        136
#define WS_FLOATS (64 * PD)
#define XS_FLOATS (128 * PD)
#define CONV_SMEM ((XS_FLOATS + 2 * WS_FLOATS) * 4)    // 139264 B

__global__ __launch_bounds__(256, 1) void conv_kernel(float* __restrict__ out)
{
    extern __shared__ __align__(16) float sm[];
    float* xs = sm;                   // [128][PD], col j <-> t = t0 - 8 + j
    float* ws = sm + XS_FLOATS;       // [2][64][PD]

    int tid = threadIdx.x, lane = tid & 31, wid = tid >> 5;
    int lk = lane & 3, lg = lane >> 2;
    int wcb = (wid >> 1) * 32;        // warp co base
    int wtb = (wid & 1) * 64;         // warp t base
    int chunk = blockIdx.x;
    int b = chunk / NK, kk = chunk % NK;
    int t0 = kk * TKC;

    // ---- stage x tile (once) ----
    const float* xbase = g_xt + (size_t)b * CI * TT;
    #pragma unroll
    for (int u = 0; u < 16; u++) {
        int i = tid + u * 256;                 // 0..4095
        int cin = i >> 5, j4 = i & 31;
        int ts = t0 - 8 + j4 * 4;
        int ok = (ts >= 0);                    // negative f4s are fully below 0
        cp16z(xs + cin * PD + j4 * 4, xbase + (size_t)cin * TT + (ok ? ts : 0), ok ? 16 : 0);
    }
    // ---- stage W s=0 (same group as x), then s=1 ----
    const float* Wc = g_W + (size_t)chunk * RD;
    {
        #pragma unroll
        for (int u = 0; u < 8; u++) {
            int i = tid + u * 256;             // 0..2047
            int r = i >> 5, c4 = i & 31;
            cp16(ws + r * PD + c4 * 4, Wc + (size_t)i * 4);
        }
        asm volatile("cp.async.commit_group;");
    }
    {
        const float* src = Wc + (size_t)64 * CO;    // s=1: tap0, cinblk1
        float* dst = ws + WS_FLOATS;
        #pragma unroll
        for (int u = 0; u < 8; u++) {
            int i = tid + u * 256;
            int r = i >> 5, c4 = i & 31;
            cp16(dst + r * PD + c4 * 4, src + (size_t)i * 4);
        }
        asm volatile("cp.async.commit_group;");
    }

    float acc[2][8][4];
    #pragma unroll
    for (int m = 0; m < 2; m++)
        #pragma unroll
        for (int n = 0; n < 8; n++)
            #pragma unroll
            for (int q = 0; q < 4; q++) acc[m][n][q] = 0.f;

    for (int s = 0; s < 6; s++) {
        if (s < 5) asm volatile("cp.async.wait_group 1;");
        else       asm volatile("cp.async.wait_group 0;");
        __syncthreads();

        int tap = s >> 1, cinblk = s & 1;
        int jo = 8 - tap;
        const float* wsb = ws + (s & 1) * WS_FLOATS;
        const float* xrow0 = xs + (cinblk * 64 + lk) * PD;

        #pragma unroll
        for (int ks = 0; ks < 8; ks++) {
            uint32_t a[2][4];
            const float* ap = wsb + (ks * 8 + lk) * PD + wcb + lg;
            #pragma unroll
            for (int m = 0; m < 2; m++) {
                const float* p = ap + m * 16;
                a[m][0] = __float_as_uint(p[0]);
                a[m][1] = __float_as_uint(p[8]);
                a[m][2] = __float_as_uint(p[4 * PD]);
                a[m][3] = __float_as_uint(p[4 * PD + 8]);
            }
            const float* bp = xrow0 + ks * 8 * PD + wtb + lg + jo;
            #pragma unroll
            for (int n = 0; n < 8; n++) {
                uint32_t b0 = __float_as_uint(bp[n * 8]);
                uint32_t b1 = __float_as_uint(bp[4 * PD + n * 8]);
                mma_tf32(acc[0][n], a[0], b0, b1);
                mma_tf32(acc[1][n], a[1], b0, b1);
            }
        }
        __syncthreads();
        if (s < 4) {
            int s2 = s + 2;
            const float* src = Wc + (size_t)((s2 >> 1) * CI + (s2 & 1) * 64) * CO;
            float* dst = ws + (s2 & 1) * WS_FLOATS;
            #pragma unroll
            for (int u = 0; u < 8; u++) {
                int i = tid + u * 256;
                int r = i >> 5, c4 = i & 31;
                cp16(dst + r * PD + c4 * 4, src + (size_t)i * 4);
            }
            asm volatile("cp.async.commit_group;");
        }
    }

    // ---- epilogue: regs -> smem (reuse xs) -> coalesced gmem ----
    float biasv[2][2];
    #pragma unroll
    for (int m = 0; m < 2; m++)
        #pragma unroll
        for (int r = 0; r < 2; r++)
            biasv[m][r] = g_bias[(size_t)chunk * CO + wcb + m * 16 + lg + r * 8];

    float* os = xs;                           // [128 co][124]
    #pragma unroll
    for (int m = 0; m < 2; m++) {
        int row0 = wcb + m * 16 + lg;
        #pragma unroll
        for (int n = 0; n < 8; n++) {
            int tl = wtb + n * 8 + 2 * lk;
            if (tl < TKC) {
                os[row0 * 124 + tl]           = acc[m][n][0] + biasv[m][0];
                os[row0 * 124 + tl + 1]       = acc[m][n][1] + biasv[m][0];
                os[(row0 + 8) * 124 + tl]     = acc[m][n][2] + biasv[m][1];
                os[(row0 + 8) * 124 + tl + 1] = acc[m][n][3] + biasv[m][1];
            }
        }
    }
    __syncthreads();
    float* ob = out + (size_t)b * CO * TT + t0;
    #pragma unroll
    for (int u = 0; u < 15; u++) {
        int i = tid + u * 256;                // 0..3839 = 128 rows x 30 f4
        int row = i / 30, c4 = i - row * 30;
        float4 v = *(const float4*)(os + row * 124 + c4 * 4);
        *(float4*)(ob + (size_t)row * TT + c4 * 4) = v;
    }
}

// ---------------------------------------------------------------------------
extern "C" void kernel_launch(void* const* d_in, const int* in_sizes, int n_in,
                              void* d_out, int out_size)
{
    const float* x   = (const float*)d_in[0];
    const float* z   = (const float*)d_in[1];
    const float* w1  = (const float*)d_in[2];
    const float* b1  = (const float*)d_in[3];
    const float* w2  = (const float*)d_in[4];
    const float* b2  = (const float*)d_in[5];
    const float* bw1 = (const float*)d_in[6];
    const float* bb1 = (const float*)d_in[7];
    const float* bw2 = (const float*)d_in[8];
    const float* bb2 = (const float*)d_in[9];
    float* out = (float*)d_out;

    cudaFuncSetAttribute(conv_kernel, cudaFuncAttributeMaxDynamicSharedMemorySize, CONV_SMEM);

    prep_kernel<<<NCH / 4, 256>>>(z, w1, b1, bw1, bb1, bw2, bb2);
    xprep_kernel<<<6000, 256>>>(x);
    wgen_kernel<<<dim3(RD / 128, (NCH + 127) / 128), 256>>>(w2, b2);
    conv_kernel<<<NCH, 256, CONV_SMEM>>>(out);
}

// round 9
// speedup vs baseline: 2.9330x; 1.3449x over previous
#include <cuda_runtime.h>
#include <cstdint>
#include <cstddef>

#define NB   4
#define ZD   64
#define NK   400
#define TT   48000
#define CI   128
#define CO   128
#define KSZ  3
#define HH   32
#define TKC  120
#define NCH  (NB*NK)                 // 1600
#define RD   (CI*KSZ*CO)             // 49152

// ---------------- device scratch ----------------
__device__ float g_W[(size_t)NCH * RD];      // tf32-rounded weights [chunk][tap*CI+cin][co]
__device__ float g_hv[NCH * HH];
__device__ float g_bias[NCH * CO];

// ---------------- helpers ----------------
__device__ __forceinline__ uint32_t s2u(const void* p) {
    uint32_t a;
    asm("{ .reg .u64 t; cvta.to.shared.u64 t, %1; cvt.u32.u64 %0, t; }" : "=r"(a) : "l"(p));
    return a;
}
__device__ __forceinline__ void cp16(void* d, const void* s) {
    asm volatile("cp.async.cg.shared.global [%0], [%1], 16;" :: "r"(s2u(d)), "l"(s));
}
__device__ __forceinline__ void cp16z(void* d, const void* s, int sz) {
    asm volatile("cp.async.cg.shared.global [%0], [%1], 16, %2;" :: "r"(s2u(d)), "l"(s), "r"(sz));
}
__device__ __forceinline__ float to_tf32(float v) {
    uint32_t r;
    asm("cvt.rna.tf32.f32 %0, %1;" : "=r"(r) : "f"(v));
    return __uint_as_float(r);
}
__device__ __forceinline__ void mma_tf32(float* d, const uint32_t* a, uint32_t b0, uint32_t b1) {
    asm volatile(
        "mma.sync.aligned.m16n8k8.row.col.f32.tf32.tf32.f32 "
        "{%0,%1,%2,%3}, {%4,%5,%6,%7}, {%8,%9}, {%0,%1,%2,%3};"
        : "+f"(d[0]), "+f"(d[1]), "+f"(d[2]), "+f"(d[3])
        : "r"(a[0]), "r"(a[1]), "r"(a[2]), "r"(a[3]), "r"(b0), "r"(b1));
}

// ---------------------------------------------------------------------------
// Kernel 1: MLP hiddens + bias. 4 chunks/block, MLP weights staged in smem.
// ---------------------------------------------------------------------------
__global__ __launch_bounds__(256) void prep_kernel(
    const float* __restrict__ z,
    const float* __restrict__ w1, const float* __restrict__ b1,
    const float* __restrict__ bw1, const float* __restrict__ bb1,
    const float* __restrict__ bw2, const float* __restrict__ bb2)
{
    __shared__ float w1s[HH * ZD], bw1s[HH * ZD], bw2s[CO * HH];
    __shared__ float zv[4][ZD], hb[4][HH];
    int tid = threadIdx.x;
    for (int i = tid; i < HH * ZD; i += 256) { w1s[i] = w1[i]; bw1s[i] = bw1[i]; }
    for (int i = tid; i < CO * HH; i += 256) bw2s[i] = bw2[i];
    int c0 = blockIdx.x * 4;
    {
        int j = tid >> 6, zi = tid & 63;
        int chunk = c0 + j, b = chunk / NK, kk = chunk % NK;
        zv[j][zi] = z[((size_t)b * ZD + zi) * NK + kk];
    }
    __syncthreads();
    if (tid < 128) {
        int j = tid >> 5, h = tid & 31;
        float s = b1[h];
        #pragma unroll 8
        for (int q = 0; q < ZD; q++) s += w1s[h * ZD + q] * zv[j][q];
        g_hv[(c0 + j) * HH + h] = fmaxf(s, 0.f);
    } else {
        int j = (tid - 128) >> 5, h = (tid - 128) & 31;
        float s = bb1[h];
        #pragma unroll 8
        for (int q = 0; q < ZD; q++) s += bw1s[h * ZD + q] * zv[j][q];
        hb[j][h] = fmaxf(s, 0.f);
    }
    __syncthreads();
    #pragma unroll
    for (int it = 0; it < 2; it++) {
        int idx = tid + it * 256;
        int j = idx >> 7, o = idx & 127;
        float s = bb2[o];
        #pragma unroll
        for (int q = 0; q < HH; q++) s += bw2s[o * HH + q] * hb[j][q];
        g_bias[(c0 + j) * CO + o] = s;
    }
}

// ---------------------------------------------------------------------------
// Kernel 2: weight-gen GEMM via tf32 mma, 3-term split for fp32-grade W:
//   W ~= w2h*hvh + w2l*hvh + w2h*hvl   (dropped term ~2^-22 relative)
// Block: 128 r x 128 chunk, K=32. 8 warps as 4(r) x 2(chunk).
// ---------------------------------------------------------------------------
#define WPD 136
#define WG_SMEM (4 * HH * WPD * 4)     // 69632 B dynamic
__global__ __launch_bounds__(256) void wgen_kernel(
    const float* __restrict__ w2, const float* __restrict__ b2)
{
    extern __shared__ __align__(16) float wsm[];
    float* ash = wsm;                   // [k=h][m=r] hi
    float* asl = wsm + HH * WPD;        // lo
    float* bsh = wsm + 2 * HH * WPD;    // [k=h][n=chunk] hi
    float* bsl = wsm + 3 * HH * WPD;    // lo
    int tid = threadIdx.x, lane = tid & 31, wid = tid >> 5;
    int lk = lane & 3, lg = lane >> 2;
    int r0 = blockIdx.x * 128;
    int c0 = blockIdx.y * 128;

    // stage A = w2 tile (k-major, hi/lo split)
    for (int i4 = tid; i4 < 1024; i4 += 256) {
        int r = i4 >> 3, h4 = i4 & 7;
        float4 v = *(const float4*)(w2 + (size_t)(r0 + r) * HH + h4 * 4);
        float f[4] = {v.x, v.y, v.z, v.w};
        #pragma unroll
        for (int q = 0; q < 4; q++) {
            float h = to_tf32(f[q]);
            ash[(h4 * 4 + q) * WPD + r] = h;
            asl[(h4 * 4 + q) * WPD + r] = to_tf32(f[q] - h);
        }
    }
    // stage B = hv tile (clamp OOB chunks, hi/lo split)
    for (int i4 = tid; i4 < 1024; i4 += 256) {
        int c = i4 >> 3, h4 = i4 & 7;
        int cc = c0 + c; if (cc >= NCH) cc = NCH - 1;
        float4 v = *(const float4*)(g_hv + (size_t)cc * HH + h4 * 4);
        float f[4] = {v.x, v.y, v.z, v.w};
        #pragma unroll
        for (int q = 0; q < 4; q++) {
            float h = to_tf32(f[q]);
            bsh[(h4 * 4 + q) * WPD + c] = h;
            bsl[(h4 * 4 + q) * WPD + c] = to_tf32(f[q] - h);
        }
    }
    __syncthreads();

    int wrb = (wid >> 1) * 32;     // warp r base (m)
    int wcb = (wid & 1) * 64;      // warp chunk base (n)

    float acc[2][8][4];
    #pragma unroll
    for (int m = 0; m < 2; m++)
        #pragma unroll
        for (int n = 0; n < 8; n++)
            #pragma unroll
            for (int q = 0; q < 4; q++) acc[m][n][q] = 0.f;

    #pragma unroll
    for (int ks = 0; ks < 4; ks++) {
        uint32_t ah[2][4], al[2][4];
        const float* aph = ash + (ks * 8 + lk) * WPD + wrb + lg;
        const float* apl = asl + (ks * 8 + lk) * WPD + wrb + lg;
        #pragma unroll
        for (int m = 0; m < 2; m++) {
            const float* p = aph + m * 16;
            ah[m][0] = __float_as_uint(p[0]);
            ah[m][1] = __float_as_uint(p[8]);
            ah[m][2] = __float_as_uint(p[4 * WPD]);
            ah[m][3] = __float_as_uint(p[4 * WPD + 8]);
            const float* q = apl + m * 16;
            al[m][0] = __float_as_uint(q[0]);
            al[m][1] = __float_as_uint(q[8]);
            al[m][2] = __float_as_uint(q[4 * WPD]);
            al[m][3] = __float_as_uint(q[4 * WPD + 8]);
        }
        const float* bph = bsh + (ks * 8 + lk) * WPD + wcb + lg;
        const float* bpl = bsl + (ks * 8 + lk) * WPD + wcb + lg;
        #pragma unroll
        for (int n = 0; n < 8; n++) {
            uint32_t bh0 = __float_as_uint(bph[n * 8]);
            uint32_t bh1 = __float_as_uint(bph[4 * WPD + n * 8]);
            uint32_t bl0 = __float_as_uint(bpl[n * 8]);
            uint32_t bl1 = __float_as_uint(bpl[4 * WPD + n * 8]);
            #pragma unroll
            for (int m = 0; m < 2; m++) {
                mma_tf32(acc[m][n], ah[m], bh0, bh1);   // hi*hi
                mma_tf32(acc[m][n], al[m], bh0, bh1);   // lo*hi
                mma_tf32(acc[m][n], ah[m], bl0, bl1);   // hi*lo
            }
        }
    }

    // epilogue: + b2[r], rna-round, store g_W[c][r]
    float b2v[2][2];
    #pragma unroll
    for (int m = 0; m < 2; m++) {
        b2v[m][0] = b2[r0 + wrb + m * 16 + lg];
        b2v[m][1] = b2[r0 + wrb + m * 16 + lg + 8];
    }
    #pragma unroll
    for (int n = 0; n < 8; n++) {
        int c = c0 + wcb + n * 8 + 2 * lk;
        if (c < NCH) {
            float* base0 = g_W + (size_t)c * RD + r0 + wrb;
            float* base1 = base0 + RD;
            #pragma unroll
            for (int m = 0; m < 2; m++) {
                int rl = m * 16 + lg;
                base0[rl]     = to_tf32(acc[m][n][0] + b2v[m][0]);
                base1[rl]     = to_tf32(acc[m][n][1] + b2v[m][0]);
                base0[rl + 8] = to_tf32(acc[m][n][2] + b2v[m][1]);
                base1[rl + 8] = to_tf32(acc[m][n][3] + b2v[m][1]);
            }
        }
    }
}

// ---------------------------------------------------------------------------
// Kernel 3: conv via mma.sync tf32. 1 CTA/chunk, 256 thr (8 warps, 4co x 2t),
// 2 CTAs/SM. x tile [128 cin][128 t] staged raw, then rna-rounded IN SMEM
// (unbiased tf32 operands). W streamed in 12 stages of [32 cin][128 co].
// ---------------------------------------------------------------------------
#define PD        136
#define WQ_FLOATS (32 * PD)                            // 4352
#define XS_FLOATS (128 * PD)                           // 17408
#define CONV_SMEM ((XS_FLOATS + 2 * WQ_FLOATS) * 4)    // 104448 B

__global__ __launch_bounds__(256, 2) void conv_kernel(
    const float* __restrict__ x, float* __restrict__ out)
{
    extern __shared__ __align__(16) float sm[];
    float* xs = sm;                   // [128][PD], col j <-> t = t0 - 8 + j
    float* ws = sm + XS_FLOATS;       // [2][32][PD]

    int tid = threadIdx.x, lane = tid & 31, wid = tid >> 5;
    int lk = lane & 3, lg = lane >> 2;
    int wcb = (wid >> 1) * 32;        // warp co base
    int wtb = (wid & 1) * 64;         // warp t base
    int chunk = blockIdx.x;
    int b = chunk / NK, kk = chunk % NK;
    int t0 = kk * TKC;

    // ---- stage x tile (raw fp32) + W stage 0 in group 0; W stage 1 group 1 ----
    const float* xbase = x + (size_t)b * CI * TT;
    #pragma unroll
    for (int u = 0; u < 16; u++) {
        int i = tid + u * 256;                 // 0..4095
        int cin = i >> 5, j4 = i & 31;
        int ts = t0 - 8 + j4 * 4;
        int ok = (ts >= 0);
        cp16z(xs + cin * PD + j4 * 4, xbase + (size_t)cin * TT + (ok ? ts : 0), ok ? 16 : 0);
    }
    const float* Wc = g_W + (size_t)chunk * RD;
    {
        #pragma unroll
        for (int u = 0; u < 4; u++) {
            int i = tid + u * 256;             // 0..1023 float4s (32x128)
            int r = i >> 5, c4 = i & 31;
            cp16(ws + r * PD + c4 * 4, Wc + (size_t)i * 4);
        }
        asm volatile("cp.async.commit_group;");
    }
    {
        const float* src = Wc + 32 * CO;       // stage 1
        float* dst = ws + WQ_FLOATS;
        #pragma unroll
        for (int u = 0; u < 4; u++) {
            int i = tid + u * 256;
            int r = i >> 5, c4 = i & 31;
            cp16(dst + r * PD + c4 * 4, src + (size_t)i * 4);
        }
        asm volatile("cp.async.commit_group;");
    }

    float acc[2][8][4];
    #pragma unroll
    for (int m = 0; m < 2; m++)
        #pragma unroll
        for (int n = 0; n < 8; n++)
            #pragma unroll
            for (int q = 0; q < 4; q++) acc[m][n][q] = 0.f;

    for (int s = 0; s < 12; s++) {
        if (s < 11) asm volatile("cp.async.wait_group 1;");
        else        asm volatile("cp.async.wait_group 0;");
        __syncthreads();

        if (s == 0) {
            // rna-round the resident x tile once (unbiased tf32 operands)
            #pragma unroll
            for (int u = 0; u < 16; u++) {
                int i = tid + u * 256;
                int cin = i >> 5, j4 = i & 31;
                float4* p = (float4*)(xs + cin * PD + j4 * 4);
                float4 v = *p;
                v.x = to_tf32(v.x); v.y = to_tf32(v.y);
                v.z = to_tf32(v.z); v.w = to_tf32(v.w);
                *p = v;
            }
            __syncthreads();
        }

        int tap = s >> 2, qq = s & 3;          // cin rows qq*32..+32
        int jo = 8 - tap;
        const float* wsb = ws + (s & 1) * WQ_FLOATS;
        const float* xrow0 = xs + (qq * 32 + lk) * PD;

        #pragma unroll
        for (int ks = 0; ks < 4; ks++) {
            uint32_t a[2][4];
            const float* ap = wsb + (ks * 8 + lk) * PD + wcb + lg;
            #pragma unroll
            for (int m = 0; m < 2; m++) {
                const float* p = ap + m * 16;
                a[m][0] = __float_as_uint(p[0]);
                a[m][1] = __float_as_uint(p[8]);
                a[m][2] = __float_as_uint(p[4 * PD]);
                a[m][3] = __float_as_uint(p[4 * PD + 8]);
            }
            const float* bp = xrow0 + ks * 8 * PD + wtb + lg + jo;
            #pragma unroll
            for (int n = 0; n < 8; n++) {
                uint32_t b0 = __float_as_uint(bp[n * 8]);
                uint32_t b1 = __float_as_uint(bp[4 * PD + n * 8]);
                mma_tf32(acc[0][n], a[0], b0, b1);
                mma_tf32(acc[1][n], a[1], b0, b1);
            }
        }
        __syncthreads();
        if (s < 10) {
            int s2 = s + 2;
            const float* src = Wc + (size_t)((s2 >> 2) * CI + (s2 & 3) * 32) * CO;
            float* dst = ws + (s2 & 1) * WQ_FLOATS;
            #pragma unroll
            for (int u = 0; u < 4; u++) {
                int i = tid + u * 256;
                int r = i >> 5, c4 = i & 31;
                cp16(dst + r * PD + c4 * 4, src + (size_t)i * 4);
            }
            asm volatile("cp.async.commit_group;");
        }
    }

    // ---- epilogue: regs -> smem (reuse xs) -> coalesced gmem ----
    float biasv[2][2];
    #pragma unroll
    for (int m = 0; m < 2; m++) {
        biasv[m][0] = g_bias[(size_t)chunk * CO + wcb + m * 16 + lg];
        biasv[m][1] = g_bias[(size_t)chunk * CO + wcb + m * 16 + lg + 8];
    }

    float* os = xs;                           // [128 co][124]
    #pragma unroll
    for (int m = 0; m < 2; m++) {
        int row0 = wcb + m * 16 + lg;
        #pragma unroll
        for (int n = 0; n < 8; n++) {
            int tl = wtb + n * 8 + 2 * lk;
            if (tl < TKC) {
                os[row0 * 124 + tl]           = acc[m][n][0] + biasv[m][0];
                os[row0 * 124 + tl + 1]       = acc[m][n][1] + biasv[m][0];
                os[(row0 + 8) * 124 + tl]     = acc[m][n][2] + biasv[m][1];
                os[(row0 + 8) * 124 + tl + 1] = acc[m][n][3] + biasv[m][1];
            }
        }
    }
    __syncthreads();
    float* ob = out + (size_t)b * CO * TT + t0;
    #pragma unroll
    for (int u = 0; u < 15; u++) {
        int i = tid + u * 256;                // 0..3839 = 128 rows x 30 f4
        int row = i / 30, c4 = i - row * 30;
        float4 v = *(const float4*)(os + row * 124 + c4 * 4);
        *(float4*)(ob + (size_t)row * TT + c4 * 4) = v;
    }
}

// ---------------------------------------------------------------------------
extern "C" void kernel_launch(void* const* d_in, const int* in_sizes, int n_in,
                              void* d_out, int out_size)
{
    const float* x   = (const float*)d_in[0];
    const float* z   = (const float*)d_in[1];
    const float* w1  = (const float*)d_in[2];
    const float* b1  = (const float*)d_in[3];
    const float* w2  = (const float*)d_in[4];
    const float* b2  = (const float*)d_in[5];
    const float* bw1 = (const float*)d_in[6];
    const float* bb1 = (const float*)d_in[7];
    const float* bw2 = (const float*)d_in[8];
    const float* bb2 = (const float*)d_in[9];
    float* out = (float*)d_out;

    cudaFuncSetAttribute(wgen_kernel, cudaFuncAttributeMaxDynamicSharedMemorySize, WG_SMEM);
    cudaFuncSetAttribute(conv_kernel, cudaFuncAttributeMaxDynamicSharedMemorySize, CONV_SMEM);

    prep_kernel<<<NCH / 4, 256>>>(z, w1, b1, bw1, bb1, bw2, bb2);
    wgen_kernel<<<dim3(RD / 128, (NCH + 127) / 128), 256, WG_SMEM>>>(w2, b2);
    conv_kernel<<<NCH, 256, CONV_SMEM>>>(x, out);
}